// round 3
// baseline (speedup 1.0000x reference)
#include <cuda_runtime.h>
#include <stdint.h>

// MXFP (E2M1-like, group=32) quantize-dequantize, bit-exact vs the JAX reference.
// Round 3: 8 float4 per thread (MLP=8 front-batched LDG.128), 4 lanes per
// group (2-shuffle width-4 butterfly instead of 3-shuffle width-8), magic-add
// RNE instead of FRND, streaming cache hints.

__device__ __forceinline__ float mxfp_q1(float x, float inv_scale, float scale) {
    float xd = x * inv_scale;                       // exact (power-of-two scale)
    uint32_t bb = __float_as_uint(xd);
    uint32_t eb = bb & 0x7F800000u;                 // exponent field
    // mans*2 = |xd| * 2^(1-e);  m2 in [2,4) for normal xd
    float m2 = fabsf(xd) * __uint_as_float(0x7F800000u - eb);
    // RNE to integer via magic constant (exact for |m2| < 2^22; matches rintf)
    float r = (m2 + 12582912.0f) - 12582912.0f;
    // x_rnd = r * 2^(e-1)
    float ra = r * __uint_as_float(eb - 0x00800000u);
    ra = fminf(fmaxf(ra, 0.5f), 6.0f);              // clamp [min_repr, max_repr]
    if (fabsf(xd) <= 0.25f) ra = 0.0f;              // lim_zero flush (handles 0/denorm/NaN paths)
    uint32_t rb = (__float_as_uint(ra) & 0x7FFFFFFFu) | (bb & 0x80000000u);
    return __uint_as_float(rb) * scale;             // exact (power-of-two scale)
}

__device__ __forceinline__ float maxabs4(float4 v) {
    return fmaxf(fmaxf(fabsf(v.x), fabsf(v.y)), fmaxf(fabsf(v.z), fabsf(v.w)));
}

__device__ __forceinline__ float4 q4(float4 v, float inv_scale, float scale) {
    float4 o;
    o.x = mxfp_q1(v.x, inv_scale, scale);
    o.y = mxfp_q1(v.y, inv_scale, scale);
    o.z = mxfp_q1(v.z, inv_scale, scale);
    o.w = mxfp_q1(v.w, inv_scale, scale);
    return o;
}

__global__ __launch_bounds__(256) void mxfp_kernel(const float4* __restrict__ in,
                                                   float4* __restrict__ out,
                                                   int slabQ, int nthreads) {
    int i = blockIdx.x * blockDim.x + threadIdx.x;
    if (i >= nthreads) return;

    // Each thread owns 8 floats (2 float4) of one group per slab, 4 slabs.
    // Group g within slab = 8 consecutive float4; lanes 4g..4g+3 own it.
    int g = i >> 2;
    int s = i & 3;
    int idxA = g * 8 + s;      // float4 index within slab
    int idxB = idxA + 4;

    // ---- front-batched: 8 independent LDG.128 ----
    float4 a[4], b[4];
#pragma unroll
    for (int c = 0; c < 4; c++) {
        a[c] = __ldcs(in + c * slabQ + idxA);
        b[c] = __ldcs(in + c * slabQ + idxB);
    }

    // ---- local max|.| over this thread's 8 floats per chunk ----
    float m[4];
#pragma unroll
    for (int c = 0; c < 4; c++)
        m[c] = fmaxf(maxabs4(a[c]), maxabs4(b[c]));

    // ---- 4 independent width-4 butterfly reductions (2 stages) ----
#pragma unroll
    for (int c = 0; c < 4; c++) m[c] = fmaxf(m[c], __shfl_xor_sync(0xFFFFFFFFu, m[c], 1));
#pragma unroll
    for (int c = 0; c < 4; c++) m[c] = fmaxf(m[c], __shfl_xor_sync(0xFFFFFFFFu, m[c], 2));

#pragma unroll
    for (int c = 0; c < 4; c++) {
        float mk = (m[c] == 0.0f) ? 1.0f : m[c];
        int e   = (int)(__float_as_uint(mk) >> 23) - 127;  // floor(log2) for normal mk
        int pot = e - 2;
        if (pot < -127) pot = -127;

        float inv_scale = __uint_as_float((uint32_t)(127 - pot) << 23);   // 2^-pot
        float scale = (pot >= -126)
                    ? __uint_as_float((uint32_t)(pot + 127) << 23)        // normal 2^pot
                    : __uint_as_float(0x00400000u);                       // denormal 2^-127

        __stcs(out + c * slabQ + idxA, q4(a[c], inv_scale, scale));
        __stcs(out + c * slabQ + idxB, q4(b[c], inv_scale, scale));
    }
}

extern "C" void kernel_launch(void* const* d_in, const int* in_sizes, int n_in,
                              void* d_out, int out_size) {
    const float4* x = (const float4*)d_in[0];
    float4* y = (float4*)d_out;
    int n4 = in_sizes[0] / 4;          // 8,388,608 float4 total
    int slabQ = n4 / 4;                // 2,097,152 float4 per slab (divides; multiple of 8)
    int nthreads = slabQ / 2;          // 1,048,576 threads, 2 float4 per slab each
    int threads = 256;
    int blocks = (nthreads + threads - 1) / threads;   // 4096
    mxfp_kernel<<<blocks, threads>>>(x, y, slabQ, nthreads);
}

// round 4
// speedup vs baseline: 1.0360x; 1.0360x over previous
#include <cuda_runtime.h>
#include <stdint.h>

// MXFP (E2M1-like, group=32) quantize-dequantize, bit-exact vs the JAX reference.
// Round 4: 8 fully-coalesced float4 per thread (8 slabs, each warp LDG.128 =
// 512B contiguous / 4 cache lines), width-8 group reduction (3 shuffles,
// stages interleaved across the 8 independent chunks), magic-add RNE,
// streaming cache hints, launch_bounds-capped regs for >=5 CTA/SM.

__device__ __forceinline__ float mxfp_q1(float x, float inv_scale, float scale) {
    float xd = x * inv_scale;                       // exact (power-of-two scale)
    uint32_t bb = __float_as_uint(xd);
    uint32_t eb = bb & 0x7F800000u;                 // exponent field
    // mans*2 = |xd| * 2^(1-e);  m2 in [2,4) for normal xd
    float m2 = fabsf(xd) * __uint_as_float(0x7F800000u - eb);
    // RNE to integer via magic constant (exact, matches rintf for this range)
    float r = (m2 + 12582912.0f) - 12582912.0f;
    // x_rnd = r * 2^(e-1)
    float ra = r * __uint_as_float(eb - 0x00800000u);
    ra = fminf(fmaxf(ra, 0.5f), 6.0f);              // clamp [min_repr, max_repr]
    if (fabsf(xd) <= 0.25f) ra = 0.0f;              // lim_zero flush (handles 0/denorm paths)
    uint32_t rb = (__float_as_uint(ra) & 0x7FFFFFFFu) | (bb & 0x80000000u);
    return __uint_as_float(rb) * scale;             // exact (power-of-two scale)
}

__device__ __forceinline__ float maxabs4(float4 v) {
    return fmaxf(fmaxf(fabsf(v.x), fabsf(v.y)), fmaxf(fabsf(v.z), fabsf(v.w)));
}

__device__ __forceinline__ float4 q4(float4 v, float inv_scale, float scale) {
    float4 o;
    o.x = mxfp_q1(v.x, inv_scale, scale);
    o.y = mxfp_q1(v.y, inv_scale, scale);
    o.z = mxfp_q1(v.z, inv_scale, scale);
    o.w = mxfp_q1(v.w, inv_scale, scale);
    return o;
}

__global__ __launch_bounds__(256, 5) void mxfp_kernel(const float4* __restrict__ in,
                                                      float4* __restrict__ out,
                                                      int slabQ) {
    int i = blockIdx.x * blockDim.x + threadIdx.x;
    if (i >= slabQ) return;

    // ---- front-batched: 8 independent, fully-coalesced LDG.128 ----
    float4 v[8];
#pragma unroll
    for (int c = 0; c < 8; c++)
        v[c] = __ldcs(in + c * slabQ + i);

    // ---- local max|.| per chunk ----
    float m[8];
#pragma unroll
    for (int c = 0; c < 8; c++)
        m[c] = maxabs4(v[c]);

    // ---- 8 independent width-8 butterfly reductions, stages interleaved ----
#pragma unroll
    for (int c = 0; c < 8; c++) m[c] = fmaxf(m[c], __shfl_xor_sync(0xFFFFFFFFu, m[c], 1));
#pragma unroll
    for (int c = 0; c < 8; c++) m[c] = fmaxf(m[c], __shfl_xor_sync(0xFFFFFFFFu, m[c], 2));
#pragma unroll
    for (int c = 0; c < 8; c++) m[c] = fmaxf(m[c], __shfl_xor_sync(0xFFFFFFFFu, m[c], 4));

#pragma unroll
    for (int c = 0; c < 8; c++) {
        float mk = (m[c] == 0.0f) ? 1.0f : m[c];
        int e   = (int)(__float_as_uint(mk) >> 23) - 127;  // floor(log2) for normal mk
        int pot = e - 2;
        if (pot < -127) pot = -127;

        float inv_scale = __uint_as_float((uint32_t)(127 - pot) << 23);   // 2^-pot
        float scale = (pot >= -126)
                    ? __uint_as_float((uint32_t)(pot + 127) << 23)        // normal 2^pot
                    : __uint_as_float(0x00400000u);                       // denormal 2^-127

        __stcs(out + c * slabQ + i, q4(v[c], inv_scale, scale));
    }
}

extern "C" void kernel_launch(void* const* d_in, const int* in_sizes, int n_in,
                              void* d_out, int out_size) {
    const float4* x = (const float4*)d_in[0];
    float4* y = (float4*)d_out;
    int n4 = in_sizes[0] / 4;          // 8,388,608 float4 total
    int slabQ = n4 / 8;                // 1,048,576 float4 per slab (multiple of 8)
    int threads = 256;
    int blocks = (slabQ + threads - 1) / threads;   // 4096
    mxfp_kernel<<<blocks, threads>>>(x, y, slabQ);
}